// round 4
// baseline (speedup 1.0000x reference)
#include <cuda_runtime.h>
#include <cuda_bf16.h>
#include <cstdint>

#define NN   50000
#define EE   600000
#define DD   128
#define DOUT 64
#define NB   ((NN + 255) / 256)

// ---------------- scratch ----------------
__device__ float g_mA[(size_t)NN * DD];
__device__ float g_mB[(size_t)NN * DD];
__device__ __nv_bfloat16 g_w1h[DD * DD], g_w1l[DD * DD];
__device__ __nv_bfloat16 g_w2h[DD * DD], g_w2l[DD * DD];
__device__ __nv_bfloat16 g_woh[DOUT * DD], g_wol[DOUT * DD];
__device__ int g_deg[NN], g_cnt[NN], g_off[NN + 1];
__device__ int g_part[NB], g_poff[NB], g_csr[EE], g_is64;

__device__ __forceinline__ uint32_t smem_u32(const void* p) {
    uint32_t a;
    asm("{ .reg .u64 t; cvta.to.shared.u64 t, %1; cvt.u32.u64 %0, t; }" : "=r"(a) : "l"(p));
    return a;
}

// ---------------- edge dtype ----------------
__device__ __forceinline__ int edge_idx(const void* ei, int which, int e) {
    if (g_is64) return (int)((const long long*)ei)[(size_t)which * EE + e];
    return ((const int*)ei)[which * EE + e];
}

// ---------------- CSR build ----------------
__global__ void zero_detect_kernel(const unsigned int* __restrict__ w) {
    int i = blockIdx.x * blockDim.x + threadIdx.x;
    if (i < NN) { g_deg[i] = 0; g_cnt[i] = 0; }
    if (i == 0) {
        int is64 = 1;
        for (int j = 1; j < 128; j += 2)
            if (w[j] != 0u) { is64 = 0; break; }
        g_is64 = is64;
    }
}
__global__ void hist_kernel(const void* ei) {
    int e = blockIdx.x * blockDim.x + threadIdx.x;
    if (e < EE) atomicAdd(&g_deg[edge_idx(ei, 1, e)], 1);
}
__global__ void partial_kernel() {
    __shared__ int sh[256];
    int t = threadIdx.x, i = blockIdx.x * 256 + t;
    sh[t] = (i < NN) ? g_deg[i] : 0;
    __syncthreads();
    for (int d = 128; d > 0; d >>= 1) {
        if (t < d) sh[t] += sh[t + d];
        __syncthreads();
    }
    if (t == 0) g_part[blockIdx.x] = sh[0];
}
__global__ void scanpart_kernel() {
    __shared__ int sh[256];
    int t = threadIdx.x;
    int v = (t < NB) ? g_part[t] : 0;
    sh[t] = v;
    __syncthreads();
    for (int d = 1; d < 256; d <<= 1) {
        int u = (t >= d) ? sh[t - d] : 0;
        __syncthreads();
        sh[t] += u;
        __syncthreads();
    }
    if (t < NB) g_poff[t] = sh[t] - v;
    if (t == 0) g_off[NN] = EE;
}
__global__ void offs_kernel() {
    __shared__ int sh[256];
    int t = threadIdx.x, i = blockIdx.x * 256 + t;
    int v = (i < NN) ? g_deg[i] : 0;
    sh[t] = v;
    __syncthreads();
    for (int d = 1; d < 256; d <<= 1) {
        int u = (t >= d) ? sh[t - d] : 0;
        __syncthreads();
        sh[t] += u;
        __syncthreads();
    }
    if (i < NN) g_off[i] = g_poff[blockIdx.x] + sh[t] - v;
}
__global__ void fill_kernel(const void* ei) {
    int e = blockIdx.x * blockDim.x + threadIdx.x;
    if (e < EE) {
        int d = edge_idx(ei, 1, e);
        int s = edge_idx(ei, 0, e);
        g_csr[g_off[d] + atomicAdd(&g_cnt[d], 1)] = s;
    }
}

// ---------------- split helpers ----------------
__device__ __forceinline__ void split2(float x, __nv_bfloat16& h, __nv_bfloat16& l) {
    h = __float2bfloat16(x);
    l = __float2bfloat16(x - __bfloat162float(h));
}

// all three weights: transpose + split in one kernel
__global__ void tw_all_kernel(const float* __restrict__ W1, const float* __restrict__ W2,
                              const float* __restrict__ Wo) {
    int i = blockIdx.x * blockDim.x + threadIdx.x;
    if (i < 16384) {
        int n = i >> 7, k = i & 127;
        split2(W1[k * DD + n], g_w1h[i], g_w1l[i]);
    } else if (i < 32768) {
        int j = i - 16384;
        int n = j >> 7, k = j & 127;
        split2(W2[k * DD + n], g_w2h[j], g_w2l[j]);
    } else if (i < 32768 + DOUT * DD) {
        int j = i - 32768;
        int n = j >> 7, k = j & 127;
        split2(Wo[k * DOUT + n], g_woh[j], g_wol[j]);
    }
}

// ---------------- K1: GEMM from fp32 x (M=128 tile, N=128), inline split ----------------
__global__ void __launch_bounds__(256) gemm_x(
    const float* __restrict__ X,
    const __nv_bfloat16* __restrict__ Bhi, const __nv_bfloat16* __restrict__ Blo,
    const float* __restrict__ bias, float* __restrict__ C)
{
    extern __shared__ char smem[];
    constexpr int N = 128;
    constexpr int AHI = 0, ALO = 32768, BHIO = 65536, BLOO = 65536 + N * 256;
    uint32_t sb = smem_u32(smem);
    int tid = threadIdx.x, wid = tid >> 5, lane = tid & 31;
    int row0 = blockIdx.x * 128;

    // stage A from fp32 with inline split
    for (int idx = tid; idx < 2048; idx += 256) {
        int r = idx >> 4, ch = idx & 15;
        int grow = row0 + r;
        __nv_bfloat16 h[8], l[8];
        if (grow < NN) {
            const float* p = X + (size_t)grow * DD + ch * 8;
            float4 v0 = *(const float4*)p, v1 = *(const float4*)(p + 4);
            split2(v0.x, h[0], l[0]); split2(v0.y, h[1], l[1]);
            split2(v0.z, h[2], l[2]); split2(v0.w, h[3], l[3]);
            split2(v1.x, h[4], l[4]); split2(v1.y, h[5], l[5]);
            split2(v1.z, h[6], l[6]); split2(v1.w, h[7], l[7]);
        } else {
#pragma unroll
            for (int j = 0; j < 8; j++) { h[j] = __float2bfloat16(0.f); l[j] = h[j]; }
        }
        int off = r * 256 + ((ch ^ (r & 7)) << 4);
        *(uint4*)(smem + AHI + off) = *(uint4*)h;
        *(uint4*)(smem + ALO + off) = *(uint4*)l;
    }
    for (int idx = tid; idx < N * 16; idx += 256) {
        int r = idx >> 4, ch = idx & 15;
        uint4 vh = *(const uint4*)(Bhi + r * DD + ch * 8);
        uint4 vl = *(const uint4*)(Blo + r * DD + ch * 8);
        int off = r * 256 + ((ch ^ (r & 7)) << 4);
        *(uint4*)(smem + BHIO + off) = vh;
        *(uint4*)(smem + BLOO + off) = vl;
    }
    __syncthreads();

    int wr = wid & 3, wc = wid >> 2;        // 4 row-warps x 2 col-warps
    constexpr int NW = 64, NF16 = 4, NF8 = 8;
    int lr = lane & 7;
    int a_half = (lane >> 3) & 1, a_kc = lane >> 4;
    uint32_t a_rb[2];
#pragma unroll
    for (int mf = 0; mf < 2; mf++)
        a_rb[mf] = (uint32_t)((wr * 32 + mf * 16 + a_half * 8 + lr) * 256);
    int b_kc = (lane >> 3) & 1, b_nh = lane >> 4;
    uint32_t b_rb[NF16];
#pragma unroll
    for (int nf = 0; nf < NF16; nf++)
        b_rb[nf] = (uint32_t)((wc * NW + nf * 16 + b_nh * 8 + lr) * 256);

    float acc[2][NF8][4];
#pragma unroll
    for (int mf = 0; mf < 2; mf++)
#pragma unroll
        for (int n8 = 0; n8 < NF8; n8++)
#pragma unroll
            for (int j = 0; j < 4; j++) acc[mf][n8][j] = 0.f;

    for (int ks = 0; ks < 24; ks++) {
        int s = ks >> 3, c0 = (ks & 7) * 2;
        uint32_t Ab = sb + (s == 2 ? ALO : AHI);
        uint32_t Bb = sb + (s == 1 ? BLOO : BHIO);
        uint32_t a[2][4];
#pragma unroll
        for (int mf = 0; mf < 2; mf++) {
            uint32_t addr = Ab + a_rb[mf] + (uint32_t)(((c0 + a_kc) ^ lr) << 4);
            asm volatile("ldmatrix.sync.aligned.m8n8.x4.shared.b16 {%0,%1,%2,%3}, [%4];"
                : "=r"(a[mf][0]), "=r"(a[mf][1]), "=r"(a[mf][2]), "=r"(a[mf][3]) : "r"(addr));
        }
#pragma unroll
        for (int nf = 0; nf < NF16; nf++) {
            uint32_t addr = Bb + b_rb[nf] + (uint32_t)(((c0 + b_kc) ^ lr) << 4);
            uint32_t b0, b1, b2, b3;
            asm volatile("ldmatrix.sync.aligned.m8n8.x4.shared.b16 {%0,%1,%2,%3}, [%4];"
                : "=r"(b0), "=r"(b1), "=r"(b2), "=r"(b3) : "r"(addr));
#pragma unroll
            for (int mf = 0; mf < 2; mf++) {
                float* c = acc[mf][2 * nf];
                asm volatile("mma.sync.aligned.m16n8k16.row.col.f32.bf16.bf16.f32 "
                    "{%0,%1,%2,%3}, {%4,%5,%6,%7}, {%8,%9}, {%0,%1,%2,%3};"
                    : "+f"(c[0]), "+f"(c[1]), "+f"(c[2]), "+f"(c[3])
                    : "r"(a[mf][0]), "r"(a[mf][1]), "r"(a[mf][2]), "r"(a[mf][3]), "r"(b0), "r"(b1));
                float* d = acc[mf][2 * nf + 1];
                asm volatile("mma.sync.aligned.m16n8k16.row.col.f32.bf16.bf16.f32 "
                    "{%0,%1,%2,%3}, {%4,%5,%6,%7}, {%8,%9}, {%0,%1,%2,%3};"
                    : "+f"(d[0]), "+f"(d[1]), "+f"(d[2]), "+f"(d[3])
                    : "r"(a[mf][0]), "r"(a[mf][1]), "r"(a[mf][2]), "r"(a[mf][3]), "r"(b2), "r"(b3));
            }
        }
    }

    int g = lane >> 2, tg = lane & 3;
#pragma unroll
    for (int mf = 0; mf < 2; mf++) {
        int r = row0 + wr * 32 + mf * 16 + g;
#pragma unroll
        for (int n8 = 0; n8 < NF8; n8++) {
            int c = wc * NW + n8 * 8 + tg * 2;
            float bx = bias[c], by = bias[c + 1];
            float* a0 = acc[mf][n8];
            if (r < NN)
                *(float2*)(C + (size_t)r * N + c) = make_float2(a0[0] + bx, a0[1] + by);
            if (r + 8 < NN)
                *(float2*)(C + (size_t)(r + 8) * N + c) = make_float2(a0[2] + bx, a0[3] + by);
        }
    }
}

// ---------------- fused gather + GEMM (M=64 node tile) ----------------
// out[r,:] = (sum_{e in CSR(r)} relu?(Min[src_e,:])) @ (Bh+Bl)^T + bias
template <int N, int RELU>
__global__ void __launch_bounds__(256) pool_fused(
    const float* __restrict__ Min,
    const __nv_bfloat16* __restrict__ Bhi, const __nv_bfloat16* __restrict__ Blo,
    const float* __restrict__ bias, float* __restrict__ Mout)
{
    extern __shared__ char smem[];
    constexpr int AHI = 0, ALO = 16384, BHIO = 32768, BLOO = 32768 + N * 256;
    uint32_t sb = smem_u32(smem);
    int tid = threadIdx.x, wid = tid >> 5, lane = tid & 31;
    int row0 = blockIdx.x * 64;

    // stage B first (loads overlap gather)
    for (int idx = tid; idx < N * 16; idx += 256) {
        int r = idx >> 4, ch = idx & 15;
        uint4 vh = *(const uint4*)(Bhi + r * DD + ch * 8);
        uint4 vl = *(const uint4*)(Blo + r * DD + ch * 8);
        int off = r * 256 + ((ch ^ (r & 7)) << 4);
        *(uint4*)(smem + BHIO + off) = vh;
        *(uint4*)(smem + BLOO + off) = vl;
    }

    // gather phase: warp w handles rows w*8 .. w*8+7 (lane covers 4 cols)
#pragma unroll
    for (int i = 0; i < 8; i++) {
        int r = wid * 8 + i;
        int node = row0 + r;
        float4 acc = make_float4(0.f, 0.f, 0.f, 0.f);
        if (node < NN) {
            int beg = g_off[node], end = g_off[node + 1];
            const float4* base = (const float4*)Min;
            int e = beg;
            for (; e + 4 <= end; e += 4) {
                int s0 = g_csr[e], s1 = g_csr[e + 1], s2 = g_csr[e + 2], s3 = g_csr[e + 3];
                float4 v0 = base[s0 * 32 + lane];
                float4 v1 = base[s1 * 32 + lane];
                float4 v2 = base[s2 * 32 + lane];
                float4 v3 = base[s3 * 32 + lane];
                acc.x += (v0.x + v1.x) + (v2.x + v3.x);
                acc.y += (v0.y + v1.y) + (v2.y + v3.y);
                acc.z += (v0.z + v1.z) + (v2.z + v3.z);
                acc.w += (v0.w + v1.w) + (v2.w + v3.w);
            }
            for (; e < end; e++) {
                float4 v = base[g_csr[e] * 32 + lane];
                acc.x += v.x; acc.y += v.y; acc.z += v.z; acc.w += v.w;
            }
            if (RELU) {
                acc.x = fmaxf(acc.x, 0.f); acc.y = fmaxf(acc.y, 0.f);
                acc.z = fmaxf(acc.z, 0.f); acc.w = fmaxf(acc.w, 0.f);
            }
        }
        __nv_bfloat16 h[4], l[4];
        split2(acc.x, h[0], l[0]); split2(acc.y, h[1], l[1]);
        split2(acc.z, h[2], l[2]); split2(acc.w, h[3], l[3]);
        int ch = lane >> 1;
        int off = r * 256 + ((ch ^ (r & 7)) << 4) + (lane & 1) * 8;
        *(uint2*)(smem + AHI + off) = *(uint2*)h;
        *(uint2*)(smem + ALO + off) = *(uint2*)l;
    }
    __syncthreads();

    // MMA phase: 2 row-warps x 4 col-warps
    int wr = wid & 1, wc = wid >> 1;
    constexpr int NW = N / 4, NF16 = NW / 16, NF8 = NW / 8;
    int lr = lane & 7;
    int a_half = (lane >> 3) & 1, a_kc = lane >> 4;
    uint32_t a_rb[2];
#pragma unroll
    for (int mf = 0; mf < 2; mf++)
        a_rb[mf] = (uint32_t)((wr * 32 + mf * 16 + a_half * 8 + lr) * 256);
    int b_kc = (lane >> 3) & 1, b_nh = lane >> 4;
    uint32_t b_rb[NF16];
#pragma unroll
    for (int nf = 0; nf < NF16; nf++)
        b_rb[nf] = (uint32_t)((wc * NW + nf * 16 + b_nh * 8 + lr) * 256);

    float acc[2][NF8][4];
#pragma unroll
    for (int mf = 0; mf < 2; mf++)
#pragma unroll
        for (int n8 = 0; n8 < NF8; n8++)
#pragma unroll
            for (int j = 0; j < 4; j++) acc[mf][n8][j] = 0.f;

    for (int ks = 0; ks < 24; ks++) {
        int s = ks >> 3, c0 = (ks & 7) * 2;
        uint32_t Ab = sb + (s == 2 ? ALO : AHI);
        uint32_t Bb = sb + (s == 1 ? BLOO : BHIO);
        uint32_t a[2][4];
#pragma unroll
        for (int mf = 0; mf < 2; mf++) {
            uint32_t addr = Ab + a_rb[mf] + (uint32_t)(((c0 + a_kc) ^ lr) << 4);
            asm volatile("ldmatrix.sync.aligned.m8n8.x4.shared.b16 {%0,%1,%2,%3}, [%4];"
                : "=r"(a[mf][0]), "=r"(a[mf][1]), "=r"(a[mf][2]), "=r"(a[mf][3]) : "r"(addr));
        }
#pragma unroll
        for (int nf = 0; nf < NF16; nf++) {
            uint32_t addr = Bb + b_rb[nf] + (uint32_t)(((c0 + b_kc) ^ lr) << 4);
            uint32_t b0, b1, b2, b3;
            asm volatile("ldmatrix.sync.aligned.m8n8.x4.shared.b16 {%0,%1,%2,%3}, [%4];"
                : "=r"(b0), "=r"(b1), "=r"(b2), "=r"(b3) : "r"(addr));
#pragma unroll
            for (int mf = 0; mf < 2; mf++) {
                float* c = acc[mf][2 * nf];
                asm volatile("mma.sync.aligned.m16n8k16.row.col.f32.bf16.bf16.f32 "
                    "{%0,%1,%2,%3}, {%4,%5,%6,%7}, {%8,%9}, {%0,%1,%2,%3};"
                    : "+f"(c[0]), "+f"(c[1]), "+f"(c[2]), "+f"(c[3])
                    : "r"(a[mf][0]), "r"(a[mf][1]), "r"(a[mf][2]), "r"(a[mf][3]), "r"(b0), "r"(b1));
                float* d = acc[mf][2 * nf + 1];
                asm volatile("mma.sync.aligned.m16n8k16.row.col.f32.bf16.bf16.f32 "
                    "{%0,%1,%2,%3}, {%4,%5,%6,%7}, {%8,%9}, {%0,%1,%2,%3};"
                    : "+f"(d[0]), "+f"(d[1]), "+f"(d[2]), "+f"(d[3])
                    : "r"(a[mf][0]), "r"(a[mf][1]), "r"(a[mf][2]), "r"(a[mf][3]), "r"(b2), "r"(b3));
            }
        }
    }

    int g = lane >> 2, tg = lane & 3;
#pragma unroll
    for (int mf = 0; mf < 2; mf++) {
        int r = row0 + wr * 32 + mf * 16 + g;
#pragma unroll
        for (int n8 = 0; n8 < NF8; n8++) {
            int c = wc * NW + n8 * 8 + tg * 2;
            float bx = bias[c], by = bias[c + 1];
            float* a0 = acc[mf][n8];
            if (r < NN)
                *(float2*)(Mout + (size_t)r * N + c) = make_float2(a0[0] + bx, a0[1] + by);
            if (r + 8 < NN)
                *(float2*)(Mout + (size_t)(r + 8) * N + c) = make_float2(a0[2] + bx, a0[3] + by);
        }
    }
}

// ---------------- launch ----------------
extern "C" void kernel_launch(void* const* d_in, const int* in_sizes, int n_in,
                              void* d_out, int out_size) {
    const float* x    = (const float*)d_in[0];
    const void*  ei   = d_in[1];
    const float* W1   = (const float*)d_in[2];
    const float* b1   = (const float*)d_in[3];
    const float* W2   = (const float*)d_in[4];
    const float* b2   = (const float*)d_in[5];
    const float* Wout = (const float*)d_in[6];
    const float* bout = (const float*)d_in[7];
    float* out = (float*)d_out;

    float *mA, *mB;
    __nv_bfloat16 *w1h, *w1l, *w2h, *w2l, *woh, *wol;
    cudaGetSymbolAddress((void**)&mA, g_mA);
    cudaGetSymbolAddress((void**)&mB, g_mB);
    cudaGetSymbolAddress((void**)&w1h, g_w1h); cudaGetSymbolAddress((void**)&w1l, g_w1l);
    cudaGetSymbolAddress((void**)&w2h, g_w2h); cudaGetSymbolAddress((void**)&w2l, g_w2l);
    cudaGetSymbolAddress((void**)&woh, g_woh); cudaGetSymbolAddress((void**)&wol, g_wol);

    const int SMX    = 131072;                 // gemm_x: 64K A + 64K B
    const int SMF128 = 32768 + 128 * 512;      // 98304
    const int SMF64  = 32768 + 64 * 512;       // 65536
    static bool attr_done = false;
    if (!attr_done) {
        cudaFuncSetAttribute(gemm_x, cudaFuncAttributeMaxDynamicSharedMemorySize, SMX);
        cudaFuncSetAttribute(pool_fused<128, 0>, cudaFuncAttributeMaxDynamicSharedMemorySize, SMF128);
        cudaFuncSetAttribute(pool_fused<128, 1>, cudaFuncAttributeMaxDynamicSharedMemorySize, SMF128);
        cudaFuncSetAttribute(pool_fused<64, 1>,  cudaFuncAttributeMaxDynamicSharedMemorySize, SMF64);
        attr_done = true;
    }

    // CSR build
    zero_detect_kernel<<<NB, 256>>>((const unsigned int*)ei);
    hist_kernel<<<(EE + 255) / 256, 256>>>(ei);
    partial_kernel<<<NB, 256>>>();
    scanpart_kernel<<<1, 256>>>();
    offs_kernel<<<NB, 256>>>();
    fill_kernel<<<(EE + 255) / 256, 256>>>(ei);

    // weight prep (one kernel)
    tw_all_kernel<<<(32768 + DOUT * DD + 255) / 256, 256>>>(W1, W2, Wout);

    const int gx = (NN + 127) / 128;   // 391
    const int gf = (NN + 63) / 64;     // 782

    // K1: m = x@W1 + b1
    gemm_x<<<gx, 256, SMX>>>(x, w1h, w1l, b1, mA);
    // K2: x1 = A(mA); m = x1@W1 + b1          (pool1 iter 2)
    pool_fused<128, 0><<<gf, 256, SMF128>>>(mA, w1h, w1l, b1, mB);
    // K3: x2 = relu(A(mB)); m = x2@W2 + b2    (relu after pool1, pool2 iter 1)
    pool_fused<128, 1><<<gf, 256, SMF128>>>(mB, w2h, w2l, b2, mA);
    // K4: x3 = A(mA); m = x3@W2 + b2          (pool2 iter 2)
    pool_fused<128, 0><<<gf, 256, SMF128>>>(mA, w2h, w2l, b2, mB);
    // K5: x4 = relu(A(mB)); out = x4@Wout + bout
    pool_fused<64, 1><<<gf, 256, SMF64>>>(mB, woh, wol, bout, out);
}

// round 5
// speedup vs baseline: 1.3487x; 1.3487x over previous
#include <cuda_runtime.h>
#include <cuda_bf16.h>
#include <cstdint>

#define NN   50000
#define EE   600000
#define DD   128
#define DOUT 64
#define NBB  196            // CSR-build blocks (256 thr each; 196*256 = 50176 >= NN)

// ---------------- scratch ----------------
__device__ float g_m[(size_t)NN * DD];
__device__ __nv_bfloat16 g_hA[(size_t)NN * DD];
__device__ __nv_bfloat16 g_lA[(size_t)NN * DD];
__device__ __nv_bfloat16 g_w1h[DD * DD], g_w1l[DD * DD];
__device__ __nv_bfloat16 g_w2h[DD * DD], g_w2l[DD * DD];
__device__ __nv_bfloat16 g_woh[DOUT * DD], g_wol[DOUT * DD];
__device__ int g_deg[NN], g_cnt[NN], g_off[NN + 1];
__device__ int g_part[NBB];
__device__ int g_csr[EE];
__device__ int g_is64;
__device__ unsigned g_gen = 0;   // monotonic across replays (safe)
__device__ unsigned g_ctr = 0;   // returns to 0 after each barrier (replay-safe)

__device__ __forceinline__ uint32_t smem_u32(const void* p) {
    uint32_t a;
    asm("{ .reg .u64 t; cvta.to.shared.u64 t, %1; cvt.u32.u64 %0, t; }" : "=r"(a) : "l"(p));
    return a;
}

// ---------------- grid barrier (all NBB blocks resident) ----------------
__device__ __forceinline__ void gbar() {
    __syncthreads();
    if (threadIdx.x == 0) {
        unsigned my = atomicAdd(&g_gen, 0u);
        __threadfence();
        unsigned old = atomicAdd(&g_ctr, 1u);
        if (old == NBB - 1) {
            atomicExch(&g_ctr, 0u);
            __threadfence();
            atomicAdd(&g_gen, 1u);
        } else {
            while (atomicAdd(&g_gen, 0u) == my) __nanosleep(64);
        }
    }
    __syncthreads();
}

__device__ __forceinline__ int edge_idx(const void* ei, int which, int e) {
    if (g_is64) return (int)((const long long*)ei)[(size_t)which * EE + e];
    return ((const int*)ei)[which * EE + e];
}

// ---------------- one-kernel CSR build ----------------
__global__ void __launch_bounds__(256) csr_build(const void* ei) {
    int tid = threadIdx.x, bid = blockIdx.x;
    int gt = bid * 256 + tid;
    const int GT = NBB * 256;

    // phase 0: zero + dtype sniff
    for (int i = gt; i < NN; i += GT) { g_deg[i] = 0; g_cnt[i] = 0; }
    if (gt == 0) {
        const unsigned int* w = (const unsigned int*)ei;
        int is64 = 1;
        for (int j = 1; j < 128; j += 2)
            if (w[j] != 0u) { is64 = 0; break; }
        g_is64 = is64;
    }
    gbar();

    // phase 1: histogram of destinations
    for (int e = gt; e < EE; e += GT)
        atomicAdd(&g_deg[edge_idx(ei, 1, e)], 1);
    gbar();

    // phase 2a: block-local scan + aggregate
    __shared__ int sh[256];
    __shared__ int sh_poff;
    int node = gt;
    int v = (node < NN) ? g_deg[node] : 0;
    sh[tid] = v;
    __syncthreads();
    for (int d = 1; d < 256; d <<= 1) {
        int u = (tid >= d) ? sh[tid - d] : 0;
        __syncthreads();
        sh[tid] += u;
        __syncthreads();
    }
    int local_incl = sh[tid];
    if (tid == 255) g_part[bid] = local_incl;
    gbar();

    // phase 2b: block prefix = sum of predecessor aggregates (reduce <=196 values)
    {
        int pv = (tid < bid) ? g_part[tid] : 0;
        sh[tid] = pv;
        __syncthreads();
        for (int d = 128; d > 0; d >>= 1) {
            if (tid < d) sh[tid] += sh[tid + d];
            __syncthreads();
        }
        if (tid == 0) sh_poff = sh[0];
        __syncthreads();
    }
    if (node < NN) g_off[node] = sh_poff + local_incl - v;
    if (gt == 0) g_off[NN] = EE;
    gbar();

    // phase 3: fill CSR
    for (int e = gt; e < EE; e += GT) {
        int d = edge_idx(ei, 1, e);
        int s = edge_idx(ei, 0, e);
        g_csr[g_off[d] + atomicAdd(&g_cnt[d], 1)] = s;
    }
}

// ---------------- split helpers ----------------
__device__ __forceinline__ void split2(float x, __nv_bfloat16& h, __nv_bfloat16& l) {
    h = __float2bfloat16(x);
    l = __float2bfloat16(x - __bfloat162float(h));
}

// all three weights: transpose + split, one kernel
__global__ void tw_all_kernel(const float* __restrict__ W1, const float* __restrict__ W2,
                              const float* __restrict__ Wo) {
    int i = blockIdx.x * blockDim.x + threadIdx.x;
    if (i < 16384) {
        int n = i >> 7, k = i & 127;
        split2(W1[k * DD + n], g_w1h[i], g_w1l[i]);
    } else if (i < 32768) {
        int j = i - 16384;
        int n = j >> 7, k = j & 127;
        split2(W2[k * DD + n], g_w2h[j], g_w2l[j]);
    } else if (i < 32768 + DOUT * DD) {
        int j = i - 32768;
        int n = j >> 7, k = j & 127;
        split2(Wo[k * DOUT + n], g_woh[j], g_wol[j]);
    }
}

// ---------------- MMA core (shared by both GEMM kernels) ----------------
// smem layout: A hi at Ab, A lo at Ab+32768; B hi at Bb, B lo at Bb+N*256.
template <int N>
__device__ __forceinline__ void mma_core(uint32_t sb, int AHI, int ALO, int BHIO, int BLOO,
                                         const float* __restrict__ bias,
                                         float* __restrict__ C, int row0,
                                         int wid, int lane, int WR /*row-warps*/) {
    int wr = (WR == 4) ? (wid & 3) : (wid & 1);
    int wc = (WR == 4) ? (wid >> 2) : (wid >> 1);
    const int NW = N / (8 / WR);       // WR=4 -> N/2 ; WR=2 -> N/4
    const int NF16 = NW / 16, NF8 = NW / 8;
    int lr = lane & 7;
    int a_half = (lane >> 3) & 1, a_kc = lane >> 4;
    uint32_t a_rb[2];
#pragma unroll
    for (int mf = 0; mf < 2; mf++)
        a_rb[mf] = (uint32_t)((wr * 32 + mf * 16 + a_half * 8 + lr) * 256);
    int b_kc = (lane >> 3) & 1, b_nh = lane >> 4;
    uint32_t b_rb[8];
#pragma unroll
    for (int nf = 0; nf < NF16; nf++)
        b_rb[nf] = (uint32_t)((wc * NW + nf * 16 + b_nh * 8 + lr) * 256);

    float acc[2][8][4];
#pragma unroll
    for (int mf = 0; mf < 2; mf++)
#pragma unroll
        for (int n8 = 0; n8 < NF8; n8++)
#pragma unroll
            for (int j = 0; j < 4; j++) acc[mf][n8][j] = 0.f;

    for (int ks = 0; ks < 24; ks++) {
        int s = ks >> 3, c0 = (ks & 7) * 2;
        uint32_t Ab = sb + (s == 2 ? ALO : AHI);
        uint32_t Bb = sb + (s == 1 ? BLOO : BHIO);
        uint32_t a[2][4];
#pragma unroll
        for (int mf = 0; mf < 2; mf++) {
            uint32_t addr = Ab + a_rb[mf] + (uint32_t)(((c0 + a_kc) ^ lr) << 4);
            asm volatile("ldmatrix.sync.aligned.m8n8.x4.shared.b16 {%0,%1,%2,%3}, [%4];"
                : "=r"(a[mf][0]), "=r"(a[mf][1]), "=r"(a[mf][2]), "=r"(a[mf][3]) : "r"(addr));
        }
#pragma unroll
        for (int nf = 0; nf < NF16; nf++) {
            uint32_t addr = Bb + b_rb[nf] + (uint32_t)(((c0 + b_kc) ^ lr) << 4);
            uint32_t b0, b1, b2, b3;
            asm volatile("ldmatrix.sync.aligned.m8n8.x4.shared.b16 {%0,%1,%2,%3}, [%4];"
                : "=r"(b0), "=r"(b1), "=r"(b2), "=r"(b3) : "r"(addr));
#pragma unroll
            for (int mf = 0; mf < 2; mf++) {
                float* c = acc[mf][2 * nf];
                asm volatile("mma.sync.aligned.m16n8k16.row.col.f32.bf16.bf16.f32 "
                    "{%0,%1,%2,%3}, {%4,%5,%6,%7}, {%8,%9}, {%0,%1,%2,%3};"
                    : "+f"(c[0]), "+f"(c[1]), "+f"(c[2]), "+f"(c[3])
                    : "r"(a[mf][0]), "r"(a[mf][1]), "r"(a[mf][2]), "r"(a[mf][3]), "r"(b0), "r"(b1));
                float* d = acc[mf][2 * nf + 1];
                asm volatile("mma.sync.aligned.m16n8k16.row.col.f32.bf16.bf16.f32 "
                    "{%0,%1,%2,%3}, {%4,%5,%6,%7}, {%8,%9}, {%0,%1,%2,%3};"
                    : "+f"(d[0]), "+f"(d[1]), "+f"(d[2]), "+f"(d[3])
                    : "r"(a[mf][0]), "r"(a[mf][1]), "r"(a[mf][2]), "r"(a[mf][3]), "r"(b2), "r"(b3));
            }
        }
    }

    int g = lane >> 2, tg = lane & 3;
#pragma unroll
    for (int mf = 0; mf < 2; mf++) {
        int r = row0 + wr * 32 + mf * 16 + g;
#pragma unroll
        for (int n8 = 0; n8 < NF8; n8++) {
            int c = wc * NW + n8 * 8 + tg * 2;
            float bx = bias[c], by = bias[c + 1];
            float* a0 = acc[mf][n8];
            if (r < NN)
                *(float2*)(C + (size_t)r * N + c) = make_float2(a0[0] + bx, a0[1] + by);
            if (r + 8 < NN)
                *(float2*)(C + (size_t)(r + 8) * N + c) = make_float2(a0[2] + bx, a0[3] + by);
        }
    }
}

// ---------------- GEMM from split planes (N=128 or 64) ----------------
template <int N>
__global__ void __launch_bounds__(256) gemm_mma(
    const __nv_bfloat16* __restrict__ Ahi, const __nv_bfloat16* __restrict__ Alo,
    const __nv_bfloat16* __restrict__ Bhi, const __nv_bfloat16* __restrict__ Blo,
    const float* __restrict__ bias, float* __restrict__ C)
{
    extern __shared__ char smem[];
    constexpr int AHI = 0, ALO = 32768, BHIO = 65536, BLOO = 65536 + N * 256;
    uint32_t sb = smem_u32(smem);
    int tid = threadIdx.x, wid = tid >> 5, lane = tid & 31;
    int row0 = blockIdx.x * 128;

    for (int idx = tid; idx < 2048; idx += 256) {
        int r = idx >> 4, ch = idx & 15;
        int grow = row0 + r;
        uint4 vh = make_uint4(0, 0, 0, 0), vl = vh;
        if (grow < NN) {
            vh = *(const uint4*)(Ahi + (size_t)grow * DD + ch * 8);
            vl = *(const uint4*)(Alo + (size_t)grow * DD + ch * 8);
        }
        int off = r * 256 + ((ch ^ (r & 7)) << 4);
        *(uint4*)(smem + AHI + off) = vh;
        *(uint4*)(smem + ALO + off) = vl;
    }
    for (int idx = tid; idx < N * 16; idx += 256) {
        int r = idx >> 4, ch = idx & 15;
        uint4 vh = *(const uint4*)(Bhi + r * DD + ch * 8);
        uint4 vl = *(const uint4*)(Blo + r * DD + ch * 8);
        int off = r * 256 + ((ch ^ (r & 7)) << 4);
        *(uint4*)(smem + BHIO + off) = vh;
        *(uint4*)(smem + BLOO + off) = vl;
    }
    __syncthreads();
    mma_core<N>(sb, AHI, ALO, BHIO, BLOO, bias, C, row0, wid, lane, 4);
}

// ---------------- GEMM head: fp32 X input, inline split (N=128) ----------------
__global__ void __launch_bounds__(256) gemm_x(
    const float* __restrict__ X,
    const __nv_bfloat16* __restrict__ Bhi, const __nv_bfloat16* __restrict__ Blo,
    const float* __restrict__ bias, float* __restrict__ C)
{
    extern __shared__ char smem[];
    constexpr int N = 128;
    constexpr int AHI = 0, ALO = 32768, BHIO = 65536, BLOO = 65536 + N * 256;
    uint32_t sb = smem_u32(smem);
    int tid = threadIdx.x, wid = tid >> 5, lane = tid & 31;
    int row0 = blockIdx.x * 128;

    for (int idx = tid; idx < 2048; idx += 256) {
        int r = idx >> 4, ch = idx & 15;
        int grow = row0 + r;
        __nv_bfloat16 h[8], l[8];
        if (grow < NN) {
            const float* p = X + (size_t)grow * DD + ch * 8;
            float4 v0 = *(const float4*)p, v1 = *(const float4*)(p + 4);
            split2(v0.x, h[0], l[0]); split2(v0.y, h[1], l[1]);
            split2(v0.z, h[2], l[2]); split2(v0.w, h[3], l[3]);
            split2(v1.x, h[4], l[4]); split2(v1.y, h[5], l[5]);
            split2(v1.z, h[6], l[6]); split2(v1.w, h[7], l[7]);
        } else {
#pragma unroll
            for (int j = 0; j < 8; j++) { h[j] = __float2bfloat16(0.f); l[j] = h[j]; }
        }
        int off = r * 256 + ((ch ^ (r & 7)) << 4);
        *(uint4*)(smem + AHI + off) = *(uint4*)h;
        *(uint4*)(smem + ALO + off) = *(uint4*)l;
    }
    for (int idx = tid; idx < N * 16; idx += 256) {
        int r = idx >> 4, ch = idx & 15;
        uint4 vh = *(const uint4*)(Bhi + r * DD + ch * 8);
        uint4 vl = *(const uint4*)(Blo + r * DD + ch * 8);
        int off = r * 256 + ((ch ^ (r & 7)) << 4);
        *(uint4*)(smem + BHIO + off) = vh;
        *(uint4*)(smem + BLOO + off) = vl;
    }
    __syncthreads();
    mma_core<N>(sb, AHI, ALO, BHIO, BLOO, bias, C, row0, wid, lane, 4);
}

// ---------------- gather-sum (warp per node) + relu + split-plane output ----------------
__global__ void gather_kernel(const float* __restrict__ m, int relu) {
    int gw = (blockIdx.x * blockDim.x + threadIdx.x) >> 5;
    int lane = threadIdx.x & 31;
    if (gw >= NN) return;
    int beg = g_off[gw], end = g_off[gw + 1];
    const float4* base = (const float4*)m;
    float4 acc = make_float4(0.f, 0.f, 0.f, 0.f);
    int e = beg;
    for (; e + 2 <= end; e += 2) {
        int s0 = g_csr[e], s1 = g_csr[e + 1];
        float4 v0 = base[s0 * 32 + lane];
        float4 v1 = base[s1 * 32 + lane];
        acc.x += v0.x + v1.x; acc.y += v0.y + v1.y;
        acc.z += v0.z + v1.z; acc.w += v0.w + v1.w;
    }
    if (e < end) {
        float4 v = base[g_csr[e] * 32 + lane];
        acc.x += v.x; acc.y += v.y; acc.z += v.z; acc.w += v.w;
    }
    if (relu) {
        acc.x = fmaxf(acc.x, 0.f); acc.y = fmaxf(acc.y, 0.f);
        acc.z = fmaxf(acc.z, 0.f); acc.w = fmaxf(acc.w, 0.f);
    }
    __nv_bfloat16 h[4], l[4];
    split2(acc.x, h[0], l[0]); split2(acc.y, h[1], l[1]);
    split2(acc.z, h[2], l[2]); split2(acc.w, h[3], l[3]);
    size_t o = ((size_t)gw * DD + lane * 4) >> 2;
    ((uint2*)g_hA)[o] = *(uint2*)h;
    ((uint2*)g_lA)[o] = *(uint2*)l;
}

// ---------------- launch ----------------
extern "C" void kernel_launch(void* const* d_in, const int* in_sizes, int n_in,
                              void* d_out, int out_size) {
    const float* x    = (const float*)d_in[0];
    const void*  ei   = d_in[1];
    const float* W1   = (const float*)d_in[2];
    const float* b1   = (const float*)d_in[3];
    const float* W2   = (const float*)d_in[4];
    const float* b2   = (const float*)d_in[5];
    const float* Wout = (const float*)d_in[6];
    const float* bout = (const float*)d_in[7];
    float* out = (float*)d_out;

    float* m;
    __nv_bfloat16 *hA, *lA, *w1h, *w1l, *w2h, *w2l, *woh, *wol;
    cudaGetSymbolAddress((void**)&m,  g_m);
    cudaGetSymbolAddress((void**)&hA, g_hA);
    cudaGetSymbolAddress((void**)&lA, g_lA);
    cudaGetSymbolAddress((void**)&w1h, g_w1h); cudaGetSymbolAddress((void**)&w1l, g_w1l);
    cudaGetSymbolAddress((void**)&w2h, g_w2h); cudaGetSymbolAddress((void**)&w2l, g_w2l);
    cudaGetSymbolAddress((void**)&woh, g_woh); cudaGetSymbolAddress((void**)&wol, g_wol);

    const int SM128 = 131072;   // 64K A planes + 64K B planes
    const int SM64  = 98304;    // 64K A planes + 32K B planes
    static bool attr_done = false;
    if (!attr_done) {
        cudaFuncSetAttribute(gemm_x, cudaFuncAttributeMaxDynamicSharedMemorySize, SM128);
        cudaFuncSetAttribute(gemm_mma<128>, cudaFuncAttributeMaxDynamicSharedMemorySize, SM128);
        cudaFuncSetAttribute(gemm_mma<64>,  cudaFuncAttributeMaxDynamicSharedMemorySize, SM64);
        attr_done = true;
    }

    // prep: weights (independent) + CSR (one kernel, internal grid barriers)
    tw_all_kernel<<<(32768 + DOUT * DD + 255) / 256, 256>>>(W1, W2, Wout);
    csr_build<<<NBB, 256>>>(ei);

    const int gx = (NN + 127) / 128;        // 391
    const int gg = (NN * 32 + 255) / 256;   // 6250 (warp per node)

    gemm_x<<<gx, 256, SM128>>>(x, w1h, w1l, b1, m);           // m = x@W1+b1
    gather_kernel<<<gg, 256>>>(m, 0);                          // h = A m
    gemm_mma<128><<<gx, 256, SM128>>>(hA, lA, w1h, w1l, b1, m);
    gather_kernel<<<gg, 256>>>(m, 1);                          // h = relu(A m)
    gemm_mma<128><<<gx, 256, SM128>>>(hA, lA, w2h, w2l, b2, m);
    gather_kernel<<<gg, 256>>>(m, 0);
    gemm_mma<128><<<gx, 256, SM128>>>(hA, lA, w2h, w2l, b2, m);
    gather_kernel<<<gg, 256>>>(m, 1);                          // h = relu(A m)
    gemm_mma<64><<<gx, 256, SM64>>>(hA, lA, woh, wol, bout, out);
}

// round 6
// speedup vs baseline: 1.4018x; 1.0394x over previous
#include <cuda_runtime.h>
#include <cuda_bf16.h>
#include <cstdint>

#define NN   50000
#define EE   600000
#define DD   128
#define DOUT 64
#define NB   ((NN + 255) / 256)   // 196

// ---------------- scratch ----------------
__device__ float g_m[(size_t)NN * DD];
__device__ __nv_bfloat16 g_hA[(size_t)NN * DD];
__device__ __nv_bfloat16 g_lA[(size_t)NN * DD];
__device__ __nv_bfloat16 g_w1h[DD * DD], g_w1l[DD * DD];
__device__ __nv_bfloat16 g_w2h[DD * DD], g_w2l[DD * DD];
__device__ __nv_bfloat16 g_woh[DOUT * DD], g_wol[DOUT * DD];
__device__ int g_deg[NN], g_cnt[NN], g_off[NN + 1];
__device__ int g_part[NB], g_poff[NB];
__device__ int g_csr[EE];
__device__ int g_is64;

__device__ __forceinline__ uint32_t smem_u32(const void* p) {
    uint32_t a;
    asm("{ .reg .u64 t; cvta.to.shared.u64 t, %1; cvt.u32.u64 %0, t; }" : "=r"(a) : "l"(p));
    return a;
}

__device__ __forceinline__ int edge_idx(const void* ei, int which, int e) {
    if (g_is64) return (int)((const long long*)ei)[(size_t)which * EE + e];
    return ((const int*)ei)[which * EE + e];
}

// ---------------- CSR build (multi-kernel, side stream) ----------------
__global__ void zero_detect_kernel(const unsigned int* __restrict__ w) {
    int i = blockIdx.x * blockDim.x + threadIdx.x;
    if (i < NN) { g_deg[i] = 0; g_cnt[i] = 0; }
    if (i == 0) {
        int is64 = 1;
        for (int j = 1; j < 128; j += 2)
            if (w[j] != 0u) { is64 = 0; break; }
        g_is64 = is64;
    }
}
__global__ void hist_kernel(const void* ei) {
    int e = blockIdx.x * blockDim.x + threadIdx.x;
    if (e < EE) atomicAdd(&g_deg[edge_idx(ei, 1, e)], 1);
}
__global__ void partial_kernel() {
    __shared__ int sh[256];
    int t = threadIdx.x, i = blockIdx.x * 256 + t;
    sh[t] = (i < NN) ? g_deg[i] : 0;
    __syncthreads();
    for (int d = 128; d > 0; d >>= 1) {
        if (t < d) sh[t] += sh[t + d];
        __syncthreads();
    }
    if (t == 0) g_part[blockIdx.x] = sh[0];
}
__global__ void scanpart_kernel() {
    __shared__ int sh[256];
    int t = threadIdx.x;
    int v = (t < NB) ? g_part[t] : 0;
    sh[t] = v;
    __syncthreads();
    for (int d = 1; d < 256; d <<= 1) {
        int u = (t >= d) ? sh[t - d] : 0;
        __syncthreads();
        sh[t] += u;
        __syncthreads();
    }
    if (t < NB) g_poff[t] = sh[t] - v;
    if (t == 0) g_off[NN] = EE;
}
__global__ void offs_kernel() {
    __shared__ int sh[256];
    int t = threadIdx.x, i = blockIdx.x * 256 + t;
    int v = (i < NN) ? g_deg[i] : 0;
    sh[t] = v;
    __syncthreads();
    for (int d = 1; d < 256; d <<= 1) {
        int u = (t >= d) ? sh[t - d] : 0;
        __syncthreads();
        sh[t] += u;
        __syncthreads();
    }
    if (i < NN) g_off[i] = g_poff[blockIdx.x] + sh[t] - v;
}
__global__ void fill_kernel(const void* ei) {
    int e = blockIdx.x * blockDim.x + threadIdx.x;
    if (e < EE) {
        int d = edge_idx(ei, 1, e);
        int s = edge_idx(ei, 0, e);
        g_csr[g_off[d] + atomicAdd(&g_cnt[d], 1)] = s;
    }
}

// ---------------- split helpers ----------------
__device__ __forceinline__ void split2(float x, __nv_bfloat16& h, __nv_bfloat16& l) {
    h = __float2bfloat16(x);
    l = __float2bfloat16(x - __bfloat162float(h));
}

__global__ void tw_all_kernel(const float* __restrict__ W1, const float* __restrict__ W2,
                              const float* __restrict__ Wo) {
    int i = blockIdx.x * blockDim.x + threadIdx.x;
    if (i < 16384) {
        int n = i >> 7, k = i & 127;
        split2(W1[k * DD + n], g_w1h[i], g_w1l[i]);
    } else if (i < 32768) {
        int j = i - 16384;
        int n = j >> 7, k = j & 127;
        split2(W2[k * DD + n], g_w2h[j], g_w2l[j]);
    } else if (i < 32768 + DOUT * DD) {
        int j = i - 32768;
        int n = j >> 7, k = j & 127;
        split2(Wo[k * DOUT + n], g_woh[j], g_wol[j]);
    }
}

// ---------------- staging (single plane; A at smem+0, B at smem+32768) ----------------
__device__ __forceinline__ void stageA_plane(char* smem, const __nv_bfloat16* __restrict__ A,
                                             int row0, int tid) {
    for (int idx = tid; idx < 2048; idx += 256) {
        int r = idx >> 4, ch = idx & 15, grow = row0 + r;
        uint4 v = make_uint4(0, 0, 0, 0);
        if (grow < NN) v = *(const uint4*)(A + (size_t)grow * DD + ch * 8);
        *(uint4*)(smem + r * 256 + ((ch ^ (r & 7)) << 4)) = v;
    }
}
// stage A from fp32 X with split; LO=0 -> hi plane, LO=1 -> lo plane
__device__ __forceinline__ void stageA_x(char* smem, const float* __restrict__ X,
                                         int row0, int tid, int LO) {
    for (int idx = tid; idx < 2048; idx += 256) {
        int r = idx >> 4, ch = idx & 15, grow = row0 + r;
        __nv_bfloat16 o[8];
        if (grow < NN) {
            const float* p = X + (size_t)grow * DD + ch * 8;
            float4 v0 = *(const float4*)p, v1 = *(const float4*)(p + 4);
            float f[8] = {v0.x, v0.y, v0.z, v0.w, v1.x, v1.y, v1.z, v1.w};
#pragma unroll
            for (int j = 0; j < 8; j++) {
                __nv_bfloat16 h, l;
                split2(f[j], h, l);
                o[j] = LO ? l : h;
            }
        } else {
#pragma unroll
            for (int j = 0; j < 8; j++) o[j] = __float2bfloat16(0.f);
        }
        *(uint4*)(smem + r * 256 + ((ch ^ (r & 7)) << 4)) = *(uint4*)o;
    }
}
template <int N>
__device__ __forceinline__ void stageB_plane(char* smem, const __nv_bfloat16* __restrict__ B,
                                             int tid) {
    for (int idx = tid; idx < N * 16; idx += 256) {
        int r = idx >> 4, ch = idx & 15;
        uint4 v = *(const uint4*)(B + r * DD + ch * 8);
        *(uint4*)(smem + 32768 + r * 256 + ((ch ^ (r & 7)) << 4)) = v;
    }
}

// ---------------- one K=128 MMA pass over current smem planes ----------------
template <int N>
__device__ __forceinline__ void mma_pass(uint32_t sb, float (&acc)[N / 8][4],
                                         int wid, int lane) {
    constexpr int NW = N / 2, NF16 = NW / 16, NF8 = NW / 8;
    int wr = wid & 3, wc = wid >> 2, lr = lane & 7;
    int a_half = (lane >> 3) & 1, a_kc = lane >> 4;
    int b_kc = (lane >> 3) & 1, b_nh = lane >> 4;
#pragma unroll
    for (int ks = 0; ks < 8; ks++) {
        int c0 = ks * 2;
        uint32_t a[2][4];
#pragma unroll
        for (int mf = 0; mf < 2; mf++) {
            uint32_t addr = sb + (uint32_t)((wr * 32 + mf * 16 + a_half * 8 + lr) * 256)
                          + (uint32_t)(((c0 + a_kc) ^ lr) << 4);
            asm volatile("ldmatrix.sync.aligned.m8n8.x4.shared.b16 {%0,%1,%2,%3}, [%4];"
                : "=r"(a[mf][0]), "=r"(a[mf][1]), "=r"(a[mf][2]), "=r"(a[mf][3]) : "r"(addr));
        }
#pragma unroll
        for (int nf = 0; nf < NF16; nf++) {
            uint32_t addr = sb + 32768u + (uint32_t)((wc * NW + nf * 16 + b_nh * 8 + lr) * 256)
                          + (uint32_t)(((c0 + b_kc) ^ lr) << 4);
            uint32_t b0, b1, b2, b3;
            asm volatile("ldmatrix.sync.aligned.m8n8.x4.shared.b16 {%0,%1,%2,%3}, [%4];"
                : "=r"(b0), "=r"(b1), "=r"(b2), "=r"(b3) : "r"(addr));
#pragma unroll
            for (int mf = 0; mf < 2; mf++) {
                float* c = acc[mf * NF8 + 2 * nf];
                asm volatile("mma.sync.aligned.m16n8k16.row.col.f32.bf16.bf16.f32 "
                    "{%0,%1,%2,%3}, {%4,%5,%6,%7}, {%8,%9}, {%0,%1,%2,%3};"
                    : "+f"(c[0]), "+f"(c[1]), "+f"(c[2]), "+f"(c[3])
                    : "r"(a[mf][0]), "r"(a[mf][1]), "r"(a[mf][2]), "r"(a[mf][3]), "r"(b0), "r"(b1));
                float* d = acc[mf * NF8 + 2 * nf + 1];
                asm volatile("mma.sync.aligned.m16n8k16.row.col.f32.bf16.bf16.f32 "
                    "{%0,%1,%2,%3}, {%4,%5,%6,%7}, {%8,%9}, {%0,%1,%2,%3};"
                    : "+f"(d[0]), "+f"(d[1]), "+f"(d[2]), "+f"(d[3])
                    : "r"(a[mf][0]), "r"(a[mf][1]), "r"(a[mf][2]), "r"(a[mf][3]), "r"(b2), "r"(b3));
            }
        }
    }
}

template <int N>
__device__ __forceinline__ void epilogue(const float* __restrict__ bias, float* __restrict__ C,
                                         int row0, float (&acc)[N / 8][4], int wid, int lane) {
    constexpr int NW = N / 2, NF8 = NW / 8;
    int wr = wid & 3, wc = wid >> 2;
    int g = lane >> 2, tg = lane & 3;
#pragma unroll
    for (int mf = 0; mf < 2; mf++) {
        int r = row0 + wr * 32 + mf * 16 + g;
#pragma unroll
        for (int n8 = 0; n8 < NF8; n8++) {
            int c = wc * NW + n8 * 8 + tg * 2;
            float bx = bias[c], by = bias[c + 1];
            float* a0 = acc[mf * NF8 + n8];
            if (r < NN)
                *(float2*)(C + (size_t)r * N + c) = make_float2(a0[0] + bx, a0[1] + by);
            if (r + 8 < NN)
                *(float2*)(C + (size_t)(r + 8) * N + c) = make_float2(a0[2] + bx, a0[3] + by);
        }
    }
}

// ---------------- GEMM from split planes, pass-staged (64KB smem, 2 CTA/SM) ----------------
template <int N>
__global__ void __launch_bounds__(256, 2) gemm_mma(
    const __nv_bfloat16* __restrict__ Ahi, const __nv_bfloat16* __restrict__ Alo,
    const __nv_bfloat16* __restrict__ Bhi, const __nv_bfloat16* __restrict__ Blo,
    const float* __restrict__ bias, float* __restrict__ C)
{
    extern __shared__ char smem[];
    uint32_t sb = smem_u32(smem);
    int tid = threadIdx.x, wid = tid >> 5, lane = tid & 31;
    int row0 = blockIdx.x * 128;

    float acc[N / 8][4];
#pragma unroll
    for (int i = 0; i < N / 8; i++)
#pragma unroll
        for (int j = 0; j < 4; j++) acc[i][j] = 0.f;

    // pass 0: Ahi * Bhi
    stageA_plane(smem, Ahi, row0, tid);
    stageB_plane<N>(smem, Bhi, tid);
    __syncthreads();
    mma_pass<N>(sb, acc, wid, lane);
    __syncthreads();
    // pass 1: Ahi * Blo
    stageB_plane<N>(smem, Blo, tid);
    __syncthreads();
    mma_pass<N>(sb, acc, wid, lane);
    __syncthreads();
    // pass 2: Alo * Bhi
    stageA_plane(smem, Alo, row0, tid);
    stageB_plane<N>(smem, Bhi, tid);
    __syncthreads();
    mma_pass<N>(sb, acc, wid, lane);

    epilogue<N>(bias, C, row0, acc, wid, lane);
}

// ---------------- head GEMM: fp32 X with inline split (N=128) ----------------
__global__ void __launch_bounds__(256, 2) gemm_x(
    const float* __restrict__ X,
    const __nv_bfloat16* __restrict__ Bhi, const __nv_bfloat16* __restrict__ Blo,
    const float* __restrict__ bias, float* __restrict__ C)
{
    extern __shared__ char smem[];
    constexpr int N = 128;
    uint32_t sb = smem_u32(smem);
    int tid = threadIdx.x, wid = tid >> 5, lane = tid & 31;
    int row0 = blockIdx.x * 128;

    float acc[N / 8][4];
#pragma unroll
    for (int i = 0; i < N / 8; i++)
#pragma unroll
        for (int j = 0; j < 4; j++) acc[i][j] = 0.f;

    stageA_x(smem, X, row0, tid, 0);
    stageB_plane<N>(smem, Bhi, tid);
    __syncthreads();
    mma_pass<N>(sb, acc, wid, lane);
    __syncthreads();
    stageB_plane<N>(smem, Blo, tid);
    __syncthreads();
    mma_pass<N>(sb, acc, wid, lane);
    __syncthreads();
    stageA_x(smem, X, row0, tid, 1);
    stageB_plane<N>(smem, Bhi, tid);
    __syncthreads();
    mma_pass<N>(sb, acc, wid, lane);

    epilogue<N>(bias, C, row0, acc, wid, lane);
}

// ---------------- gather-sum (warp per node, unroll 4) ----------------
__global__ void gather_kernel(const float* __restrict__ m, int relu) {
    int gw = (blockIdx.x * blockDim.x + threadIdx.x) >> 5;
    int lane = threadIdx.x & 31;
    if (gw >= NN) return;
    int beg = g_off[gw], end = g_off[gw + 1];
    const float4* base = (const float4*)m;
    float4 acc = make_float4(0.f, 0.f, 0.f, 0.f);
    int e = beg;
    for (; e + 4 <= end; e += 4) {
        int s0 = g_csr[e], s1 = g_csr[e + 1], s2 = g_csr[e + 2], s3 = g_csr[e + 3];
        float4 v0 = base[s0 * 32 + lane];
        float4 v1 = base[s1 * 32 + lane];
        float4 v2 = base[s2 * 32 + lane];
        float4 v3 = base[s3 * 32 + lane];
        acc.x += (v0.x + v1.x) + (v2.x + v3.x);
        acc.y += (v0.y + v1.y) + (v2.y + v3.y);
        acc.z += (v0.z + v1.z) + (v2.z + v3.z);
        acc.w += (v0.w + v1.w) + (v2.w + v3.w);
    }
    for (; e < end; e++) {
        float4 v = base[g_csr[e] * 32 + lane];
        acc.x += v.x; acc.y += v.y; acc.z += v.z; acc.w += v.w;
    }
    if (relu) {
        acc.x = fmaxf(acc.x, 0.f); acc.y = fmaxf(acc.y, 0.f);
        acc.z = fmaxf(acc.z, 0.f); acc.w = fmaxf(acc.w, 0.f);
    }
    __nv_bfloat16 h[4], l[4];
    split2(acc.x, h[0], l[0]); split2(acc.y, h[1], l[1]);
    split2(acc.z, h[2], l[2]); split2(acc.w, h[3], l[3]);
    size_t o = ((size_t)gw * DD + lane * 4) >> 2;
    ((uint2*)g_hA)[o] = *(uint2*)h;
    ((uint2*)g_lA)[o] = *(uint2*)l;
}

// ---------------- launch ----------------
extern "C" void kernel_launch(void* const* d_in, const int* in_sizes, int n_in,
                              void* d_out, int out_size) {
    const float* x    = (const float*)d_in[0];
    const void*  ei   = d_in[1];
    const float* W1   = (const float*)d_in[2];
    const float* b1   = (const float*)d_in[3];
    const float* W2   = (const float*)d_in[4];
    const float* b2   = (const float*)d_in[5];
    const float* Wout = (const float*)d_in[6];
    const float* bout = (const float*)d_in[7];
    float* out = (float*)d_out;

    float* m;
    __nv_bfloat16 *hA, *lA, *w1h, *w1l, *w2h, *w2l, *woh, *wol;
    cudaGetSymbolAddress((void**)&m,  g_m);
    cudaGetSymbolAddress((void**)&hA, g_hA);
    cudaGetSymbolAddress((void**)&lA, g_lA);
    cudaGetSymbolAddress((void**)&w1h, g_w1h); cudaGetSymbolAddress((void**)&w1l, g_w1l);
    cudaGetSymbolAddress((void**)&w2h, g_w2h); cudaGetSymbolAddress((void**)&w2l, g_w2l);
    cudaGetSymbolAddress((void**)&woh, g_woh); cudaGetSymbolAddress((void**)&wol, g_wol);

    const int SM128 = 65536;   // 32K A + 32K B
    const int SM64  = 49152;   // 32K A + 16K B
    static cudaStream_t s2 = nullptr;
    static cudaEvent_t evF = nullptr, evJ = nullptr;
    if (!s2) {
        cudaFuncSetAttribute(gemm_x, cudaFuncAttributeMaxDynamicSharedMemorySize, SM128);
        cudaFuncSetAttribute(gemm_mma<128>, cudaFuncAttributeMaxDynamicSharedMemorySize, SM128);
        cudaFuncSetAttribute(gemm_mma<64>,  cudaFuncAttributeMaxDynamicSharedMemorySize, SM64);
        cudaStreamCreateWithFlags(&s2, cudaStreamNonBlocking);
        cudaEventCreateWithFlags(&evF, cudaEventDisableTiming);
        cudaEventCreateWithFlags(&evJ, cudaEventDisableTiming);
    }

    // fork: CSR build on side stream, overlapped with weight prep + head GEMM
    cudaEventRecord(evF, 0);
    cudaStreamWaitEvent(s2, evF, 0);
    zero_detect_kernel<<<NB, 256, 0, s2>>>((const unsigned int*)ei);
    hist_kernel<<<(EE + 255) / 256, 256, 0, s2>>>(ei);
    partial_kernel<<<NB, 256, 0, s2>>>();
    scanpart_kernel<<<1, 256, 0, s2>>>();
    offs_kernel<<<NB, 256, 0, s2>>>();
    fill_kernel<<<(EE + 255) / 256, 256, 0, s2>>>(ei);
    cudaEventRecord(evJ, s2);

    // main stream: weights + head GEMM (independent of CSR)
    tw_all_kernel<<<(32768 + DOUT * DD + 255) / 256, 256>>>(W1, W2, Wout);

    const int gx = (NN + 127) / 128;        // 391
    const int gg = (NN * 32 + 255) / 256;   // 6250

    gemm_x<<<gx, 256, SM128>>>(x, w1h, w1l, b1, m);           // m = x@W1+b1

    // join: CSR must be ready before first gather
    cudaStreamWaitEvent(0, evJ, 0);

    gather_kernel<<<gg, 256>>>(m, 0);
    gemm_mma<128><<<gx, 256, SM128>>>(hA, lA, w1h, w1l, b1, m);
    gather_kernel<<<gg, 256>>>(m, 1);       // relu after pool 1
    gemm_mma<128><<<gx, 256, SM128>>>(hA, lA, w2h, w2l, b2, m);
    gather_kernel<<<gg, 256>>>(m, 0);
    gemm_mma<128><<<gx, 256, SM128>>>(hA, lA, w2h, w2l, b2, m);
    gather_kernel<<<gg, 256>>>(m, 1);       // relu after pool 2
    gemm_mma<64><<<gx, 256, SM64>>>(hA, lA, woh, wol, bout, out);
}